// round 6
// baseline (speedup 1.0000x reference)
#include <cuda_runtime.h>
#include <cstdint>

#define Bn   16
#define ND   8192
#define NE   16384
#define NEDGE 65536
#define H    128
#define KC   32

typedef unsigned long long u64;
typedef unsigned int u32;

// ---------------- scratch ----------------
__device__ float g_Y[(size_t)Bn * ND * H];       // hD @ W_d2e^T
__device__ float g_aggPre[(size_t)Bn * ND * H];  // mean gather hE_new
__device__ u64   g_W[4][H * H];                  // packed tf32 (lo32=hi part, hi32=lo part), layout [c][k]

__device__ int g_cntE[NE];
__device__ int g_offE[NE + 1];
__device__ int g_curE[NE];
__device__ int g_lstE[NEDGE];

__device__ int g_cntD[ND];
__device__ int g_offD[ND + 1];
__device__ int g_curD[ND];
__device__ int g_lstD[NEDGE];

// ---------------- helpers ----------------
__device__ __forceinline__ u32 f2tf32(float x) {
    u32 r;
    asm("cvt.rna.tf32.f32 %0, %1;" : "=r"(r) : "f"(x));
    return r;
}
__device__ __forceinline__ u32 swz(u32 off) { return off ^ ((off >> 3) & 0x70); }

__device__ __forceinline__ void mma8(float* d, u32 a0, u32 a1, u32 a2, u32 a3,
                                     u32 b0, u32 b1) {
    asm volatile(
        "mma.sync.aligned.m16n8k8.row.col.f32.tf32.tf32.f32 "
        "{%0,%1,%2,%3}, {%4,%5,%6,%7}, {%8,%9}, {%0,%1,%2,%3};"
        : "+f"(d[0]), "+f"(d[1]), "+f"(d[2]), "+f"(d[3])
        : "r"(a0), "r"(a1), "r"(a2), "r"(a3), "r"(b0), "r"(b1));
}

// ---------------- setup kernels ----------------
__global__ void k_wsplit(const float* __restrict__ W0, const float* __restrict__ W1,
                         const float* __restrict__ W2, const float* __restrict__ W3) {
    int gidx = blockIdx.x * 256 + threadIdx.x;     // 0..65535
    int m = gidx >> 14;
    int idx = gidx & 16383;
    const float* W = (m == 0) ? W0 : (m == 1) ? W1 : (m == 2) ? W2 : W3;
    float w = W[idx];
    u32 h = f2tf32(w);
    u32 lo = f2tf32(w - __uint_as_float(h));
    g_W[m][idx] = ((u64)lo << 32) | h;
}

__global__ void k_zero() {
    int i = blockIdx.x * 256 + threadIdx.x;
    if (i < NE) g_cntE[i] = 0;
    if (i < ND) g_cntD[i] = 0;
}

__global__ void k_count(const int* __restrict__ e_d2e, const int* __restrict__ e_e2d) {
    int e = blockIdx.x * blockDim.x + threadIdx.x;
    if (e >= NEDGE) return;
    atomicAdd(&g_cntE[e_d2e[NEDGE + e]], 1);
    atomicAdd(&g_cntD[e_e2d[NEDGE + e]], 1);
}

__global__ void k_scan2() {
    const int* cnt = blockIdx.x ? g_cntD : g_cntE;
    int* off       = blockIdx.x ? g_offD : g_offE;
    int* cur       = blockIdx.x ? g_curD : g_curE;
    const int n    = blockIdx.x ? ND : NE;
    const int m    = n / 1024;
    int t = threadIdx.x, lane = t & 31, wid = t >> 5;
    int base = t * m;
    int loc[16];
    int tot = 0;
#pragma unroll
    for (int i = 0; i < 16; i++)
        if (i < m) { loc[i] = cnt[base + i]; tot += loc[i]; }
    int s = tot;
#pragma unroll
    for (int o = 1; o < 32; o <<= 1) {
        int v = __shfl_up_sync(0xffffffffu, s, o);
        if (lane >= o) s += v;
    }
    __shared__ int wsum[32];
    if (lane == 31) wsum[wid] = s;
    __syncthreads();
    if (wid == 0) {
        int v = wsum[lane];
#pragma unroll
        for (int o = 1; o < 32; o <<= 1) {
            int u = __shfl_up_sync(0xffffffffu, v, o);
            if (lane >= o) v += u;
        }
        wsum[lane] = v;
    }
    __syncthreads();
    int add = wid ? wsum[wid - 1] : 0;
    int run = add + s - tot;
#pragma unroll
    for (int i = 0; i < 16; i++)
        if (i < m) {
            off[base + i] = run;
            cur[base + i] = run;
            run += loc[i];
        }
    if (t == 1023) off[n] = run;
}

__global__ void k_fill(const int* __restrict__ e_d2e, const int* __restrict__ e_e2d) {
    int e = blockIdx.x * blockDim.x + threadIdx.x;
    if (e >= NEDGE) return;
    {
        int d = e_d2e[NEDGE + e];
        int p = atomicAdd(&g_curE[d], 1);
        g_lstE[p] = e_d2e[e];
    }
    {
        int d = e_e2d[NEDGE + e];
        int p = atomicAdd(&g_curD[d], 1);
        g_lstD[p] = e_e2d[e];
    }
}

// ---------------- mean-gather: warp per (node, batch) ----------------
__global__ void k_agg(const float* __restrict__ SRC, const int* __restrict__ off,
                      const int* __restrict__ lst, float* __restrict__ agg,
                      int nNodes, long srcStride) {
    int gw = (blockIdx.x * blockDim.x + threadIdx.x) >> 5;
    if (gw >= nNodes * Bn) return;
    int node = gw % nNodes;
    int b    = gw / nNodes;
    int lane = threadIdx.x & 31;

    int s = off[node], e = off[node + 1];
    float4 a = make_float4(0.f, 0.f, 0.f, 0.f);
    const float* base = SRC + (size_t)b * srcStride;
    for (int j = s; j < e; ++j) {
        int src = lst[j];
        float4 v = reinterpret_cast<const float4*>(base + (size_t)src * H)[lane];
        a.x += v.x; a.y += v.y; a.z += v.z; a.w += v.w;
    }
    float sc = 1.0f / fmaxf((float)(e - s), 1.0f);
    a.x *= sc; a.y *= sc; a.z *= sc; a.w *= sc;
    reinterpret_cast<float4*>(agg + ((size_t)b * nNodes + node) * H)[lane] = a;
}

// ---------------- tf32x3 mma.sync GEMM ----------------
// 256 thr, 128x128 tile, warps 4(M) x 2(N), each warp 32x64 via m16n8k8 frags.
// smem: saB = X chunk 128x32 (u64 hi/lo interleaved, SW128), 32KB
//       sbB = W chunk 128x32 (u64), 32KB ; sOut overlays (128x136 f32 = 68KB)
// MODE 0: out = X @ W1^T
// MODE 1: out = LN(X + relu(X@W1^T + gatherY*sc + bias))*gamma + beta  (A = Y base)
// MODE 2: out = LN(X + relu(X@W1^T + A@W2^T + bias))*gamma + beta
#define SMEM_BYTES 69632

template <int MODE>
__global__ void __launch_bounds__(256, 2)
k_mma(const float* __restrict__ X, const u64* __restrict__ W1,
      const float* __restrict__ A, const u64* __restrict__ W2,
      const int* __restrict__ off, const int* __restrict__ lst,
      const float* __restrict__ ew,
      const float* __restrict__ bias, const float* __restrict__ gamma,
      const float* __restrict__ beta, float* __restrict__ out) {
    extern __shared__ char smraw[];
    char* saB = smraw;
    char* sbB = smraw + 32768;
    float* sOut = reinterpret_cast<float*>(smraw);

    const int t = threadIdx.x;
    const int lane = t & 31, wid = t >> 5;
    const int g = lane >> 2, l4 = lane & 3;
    const int wm = wid & 3, wn = wid >> 2;
    const size_t row0 = (size_t)blockIdx.x * 128;

    float acc[2][8][4];
#pragma unroll
    for (int mf = 0; mf < 2; mf++)
#pragma unroll
        for (int nf = 0; nf < 8; nf++)
#pragma unroll
            for (int q = 0; q < 4; q++) acc[mf][nf][q] = 0.f;

    const int nPass = (MODE == 2) ? 2 : 1;
    for (int p = 0; p < nPass; p++) {
        const float* src = p ? A : X;
        const u64* Wg = p ? W2 : W1;
        for (int s = 0; s < 4; s++) {
            __syncthreads();
            // ---- load X chunk (fp32 -> tf32 hi/lo packed u64, swizzled) ----
#pragma unroll
            for (int i = 0; i < 4; i++) {
                int idx = t + 256 * i;          // 1024 float4s
                int row = idx >> 3, c4 = idx & 7;
                float4 v = *reinterpret_cast<const float4*>(
                    src + (row0 + row) * H + s * KC + c4 * 4);
                float vv[4] = {v.x, v.y, v.z, v.w};
#pragma unroll
                for (int m = 0; m < 4; m++) {
                    u32 h = f2tf32(vv[m]);
                    u32 lo = f2tf32(vv[m] - __uint_as_float(h));
                    u32 o = swz((u32)(row * 256 + (c4 * 4 + m) * 8));
                    *reinterpret_cast<uint2*>(saB + o) = make_uint2(h, lo);
                }
            }
            // ---- load W chunk (pre-packed u64, swizzled) ----
#pragma unroll
            for (int i = 0; i < 16; i++) {
                int idx = t + 256 * i;          // 4096 u64s
                int row = idx >> 5, k = idx & 31;
                u64 w = Wg[(size_t)row * H + s * KC + k];
                u32 o = swz((u32)(row * 256 + k * 8));
                *reinterpret_cast<u64*>(sbB + o) = w;
            }
            __syncthreads();
            // ---- 4 ksteps of m16n8k8, 3-product tf32 split ----
#pragma unroll
            for (int ks = 0; ks < 4; ks++) {
                const int k0 = ks * 8;
                u32 ah[2][4], al[2][4];
#pragma unroll
                for (int mf = 0; mf < 2; mf++) {
                    int rb = wm * 32 + mf * 16;
                    uint2 v0 = *reinterpret_cast<const uint2*>(saB + swz((u32)((rb + g) * 256 + (k0 + l4) * 8)));
                    uint2 v1 = *reinterpret_cast<const uint2*>(saB + swz((u32)((rb + g + 8) * 256 + (k0 + l4) * 8)));
                    uint2 v2 = *reinterpret_cast<const uint2*>(saB + swz((u32)((rb + g) * 256 + (k0 + 4 + l4) * 8)));
                    uint2 v3 = *reinterpret_cast<const uint2*>(saB + swz((u32)((rb + g + 8) * 256 + (k0 + 4 + l4) * 8)));
                    ah[mf][0] = v0.x; al[mf][0] = v0.y;
                    ah[mf][1] = v1.x; al[mf][1] = v1.y;
                    ah[mf][2] = v2.x; al[mf][2] = v2.y;
                    ah[mf][3] = v3.x; al[mf][3] = v3.y;
                }
#pragma unroll
                for (int nh = 0; nh < 2; nh++) {
                    u32 bh[4][2], bl[4][2];
#pragma unroll
                    for (int q = 0; q < 4; q++) {
                        int cb = wn * 64 + (nh * 4 + q) * 8 + g;
                        uint2 w0 = *reinterpret_cast<const uint2*>(sbB + swz((u32)(cb * 256 + (k0 + l4) * 8)));
                        uint2 w1 = *reinterpret_cast<const uint2*>(sbB + swz((u32)(cb * 256 + (k0 + 4 + l4) * 8)));
                        bh[q][0] = w0.x; bl[q][0] = w0.y;
                        bh[q][1] = w1.x; bl[q][1] = w1.y;
                    }
#pragma unroll
                    for (int q = 0; q < 4; q++) {
                        int nf = nh * 4 + q;
#pragma unroll
                        for (int mf = 0; mf < 2; mf++) {
                            float* d = acc[mf][nf];
                            mma8(d, ah[mf][0], ah[mf][1], ah[mf][2], ah[mf][3], bh[q][0], bh[q][1]);
                            mma8(d, ah[mf][0], ah[mf][1], ah[mf][2], ah[mf][3], bl[q][0], bl[q][1]);
                            mma8(d, al[mf][0], al[mf][1], al[mf][2], al[mf][3], bh[q][0], bh[q][1]);
                        }
                    }
                }
            }
        }
    }

    // ---- stage acc -> sOut ----
    __syncthreads();
#pragma unroll
    for (int mf = 0; mf < 2; mf++)
#pragma unroll
        for (int nf = 0; nf < 8; nf++) {
            int r = wm * 32 + mf * 16 + g;
            int c = wn * 64 + nf * 8 + 2 * l4;
            *reinterpret_cast<float2*>(&sOut[r * 136 + c]) =
                make_float2(acc[mf][nf][0], acc[mf][nf][1]);
            *reinterpret_cast<float2*>(&sOut[(r + 8) * 136 + c]) =
                make_float2(acc[mf][nf][2], acc[mf][nf][3]);
        }
    __syncthreads();

    // ---- writer: thread t -> (row = t>>1, half = t&1) 64 cols ----
    const int row = t >> 1, half = t & 1;
    const size_t grow = row0 + row;
    float* so = sOut + row * 136 + half * 64;

    if (MODE == 0) {
        float4* og = reinterpret_cast<float4*>(out + grow * H + half * 64);
#pragma unroll
        for (int i = 0; i < 16; i++) og[i] = *reinterpret_cast<float4*>(so + i * 4);
        return;
    }

    int s0 = 0, e1 = 0;
    float sc = 0.f;
    const float* Yb = nullptr;
    if (MODE == 1) {
        int b = (int)(row0 / NE);
        int e = (int)(row0 % NE) + row;
        s0 = off[e]; e1 = off[e + 1];
        sc = (1.0f / (1.0f + __expf(-ew[e]))) / fmaxf((float)(e1 - s0), 1.0f);
        Yb = A + (size_t)b * ND * H;
    }

    float ssum = 0.f, qsum = 0.f;
#pragma unroll
    for (int pp = 0; pp < 2; pp++) {
        const int coff = half * 64 + pp * 32;
        float4 ag[8];
#pragma unroll
        for (int q = 0; q < 8; q++) ag[q] = make_float4(0.f, 0.f, 0.f, 0.f);
        if (MODE == 1) {
            for (int j = s0; j < e1; j++) {
                const float4* yr = reinterpret_cast<const float4*>(Yb + (size_t)lst[j] * H + coff);
#pragma unroll
                for (int q = 0; q < 8; q++) {
                    float4 v = yr[q];
                    ag[q].x += v.x; ag[q].y += v.y; ag[q].z += v.z; ag[q].w += v.w;
                }
            }
        }
        const float4* xr = reinterpret_cast<const float4*>(X + grow * H + coff);
        const float4* br = reinterpret_cast<const float4*>(bias + coff);
#pragma unroll
        for (int q = 0; q < 8; q++) {
            float4 d = *reinterpret_cast<float4*>(so + pp * 32 + q * 4);
            float4 xv = xr[q];
            float4 bv = br[q];
            float t0 = d.x + bv.x, t1 = d.y + bv.y, t2 = d.z + bv.z, t3 = d.w + bv.w;
            if (MODE == 1) {
                t0 += ag[q].x * sc; t1 += ag[q].y * sc;
                t2 += ag[q].z * sc; t3 += ag[q].w * sc;
            }
            t0 = fmaxf(t0, 0.f) + xv.x;
            t1 = fmaxf(t1, 0.f) + xv.y;
            t2 = fmaxf(t2, 0.f) + xv.z;
            t3 = fmaxf(t3, 0.f) + xv.w;
            *reinterpret_cast<float4*>(so + pp * 32 + q * 4) = make_float4(t0, t1, t2, t3);
            ssum += t0 + t1 + t2 + t3;
            qsum += t0 * t0 + t1 * t1 + t2 * t2 + t3 * t3;
        }
    }
    ssum += __shfl_xor_sync(0xffffffffu, ssum, 1);
    qsum += __shfl_xor_sync(0xffffffffu, qsum, 1);
    float m = ssum * (1.0f / 128.0f);
    float rstd = rsqrtf(qsum * (1.0f / 128.0f) - m * m + 1e-5f);

    const float4* gr = reinterpret_cast<const float4*>(gamma + half * 64);
    const float4* ber = reinterpret_cast<const float4*>(beta + half * 64);
    float4* og = reinterpret_cast<float4*>(out + grow * H + half * 64);
#pragma unroll
    for (int q = 0; q < 16; q++) {
        float4 tv = *reinterpret_cast<float4*>(so + q * 4);
        float4 gv = gr[q];
        float4 bev = ber[q];
        float4 o;
        o.x = (tv.x - m) * rstd * gv.x + bev.x;
        o.y = (tv.y - m) * rstd * gv.y + bev.y;
        o.z = (tv.z - m) * rstd * gv.z + bev.z;
        o.w = (tv.w - m) * rstd * gv.w + bev.w;
        og[q] = o;
    }
}

// ---------------- launch ----------------
extern "C" void kernel_launch(void* const* d_in, const int* in_sizes, int n_in,
                              void* d_out, int out_size) {
    const float* hD    = (const float*)d_in[0];
    const float* hE    = (const float*)d_in[1];
    const int*   e_d2e = (const int*)d_in[2];
    const int*   e_e2d = (const int*)d_in[3];
    const float* ew    = (const float*)d_in[4];
    const float* W_d2e    = (const float*)d_in[5];
    const float* W_e_self = (const float*)d_in[6];
    const float* b_e   = (const float*)d_in[7];
    const float* g_e   = (const float*)d_in[8];
    const float* be_e  = (const float*)d_in[9];
    const float* W_e2d    = (const float*)d_in[10];
    const float* W_d_self = (const float*)d_in[11];
    const float* b_d   = (const float*)d_in[12];
    const float* g_d   = (const float*)d_in[13];
    const float* be_d  = (const float*)d_in[14];

    float* out_hD = (float*)d_out;
    float* out_hE = (float*)d_out + (size_t)Bn * ND * H;

    float *pY, *pAggPre;
    u64* pW;
    int *pOffE, *pLstE, *pOffD, *pLstD;
    cudaGetSymbolAddress((void**)&pY, g_Y);
    cudaGetSymbolAddress((void**)&pAggPre, g_aggPre);
    cudaGetSymbolAddress((void**)&pW, g_W);
    cudaGetSymbolAddress((void**)&pOffE, g_offE);
    cudaGetSymbolAddress((void**)&pLstE, g_lstE);
    cudaGetSymbolAddress((void**)&pOffD, g_offD);
    cudaGetSymbolAddress((void**)&pLstD, g_lstD);

    const u64* W0 = pW + 0 * H * H;   // W_d2e
    const u64* W1 = pW + 1 * H * H;   // W_e_self
    const u64* W2 = pW + 2 * H * H;   // W_e2d
    const u64* W3 = pW + 3 * H * H;   // W_d_self

    cudaFuncSetAttribute(k_mma<0>, cudaFuncAttributeMaxDynamicSharedMemorySize, SMEM_BYTES);
    cudaFuncSetAttribute(k_mma<1>, cudaFuncAttributeMaxDynamicSharedMemorySize, SMEM_BYTES);
    cudaFuncSetAttribute(k_mma<2>, cudaFuncAttributeMaxDynamicSharedMemorySize, SMEM_BYTES);

    // ---- setup: weight splits + CSR ----
    k_wsplit<<<256, 256>>>(W_d2e, W_e_self, W_e2d, W_d_self);
    k_zero<<<NE / 256, 256>>>();
    k_count<<<NEDGE / 256, 256>>>(e_d2e, e_e2d);
    k_scan2<<<2, 1024>>>();
    k_fill<<<NEDGE / 256, 256>>>(e_d2e, e_e2d);

    // ---- Phase 1: D -> E ----
    k_mma<0><<<(Bn * ND) / 128, 256, SMEM_BYTES>>>(
        hD, W0, nullptr, nullptr, nullptr, nullptr, nullptr,
        nullptr, nullptr, nullptr, pY);
    k_mma<1><<<(Bn * NE) / 128, 256, SMEM_BYTES>>>(
        hE, W1, pY, nullptr, pOffE, pLstE, ew,
        b_e, g_e, be_e, out_hE);

    // ---- Phase 2: E -> D (commuted aggregation + dual product) ----
    k_agg<<<(ND * Bn * 32) / 256, 256>>>(out_hE, pOffD, pLstD, pAggPre, ND, (long)NE * H);
    k_mma<2><<<(Bn * ND) / 128, 256, SMEM_BYTES>>>(
        hD, W3, pAggPre, W2, nullptr, nullptr, nullptr,
        b_d, g_d, be_d, out_hD);
}

// round 8
// speedup vs baseline: 1.5043x; 1.5043x over previous
#include <cuda_runtime.h>
#include <cstdint>

#define Bn   16
#define ND   8192
#define NE   16384
#define NEDGE 65536
#define H    128
#define CAP  64     // max bucket capacity per node (max degree ~30, P(>64)~0)

typedef unsigned long long u64;

// ---------------- scratch ----------------
__device__ float g_Y[(size_t)Bn * ND * H];       // hD @ W_d2e^T
__device__ float g_aggPre[(size_t)Bn * ND * H];  // mean gather hE_new
__device__ float g_Wt[4 * H * H];                // transposed weights [k][c]

__device__ int g_cntE[NE];
__device__ int g_lstE[NE * CAP];
__device__ int g_cntD[ND];
__device__ int g_lstD[ND * CAP];

// ---------------- setup: weight transpose + counter zero (one kernel) --------
__global__ void k_prep(const float* __restrict__ W0, const float* __restrict__ W1,
                       const float* __restrict__ W2, const float* __restrict__ W3,
                       float* __restrict__ Wt) {
    int g = blockIdx.x * 256 + threadIdx.x;        // 0..65535
    int m = g >> 14;
    int idx = g & 16383;
    int k = idx >> 7, c = idx & 127;
    const float* W = (m == 0) ? W0 : (m == 1) ? W1 : (m == 2) ? W2 : W3;
    Wt[g] = W[c * H + k];
    if (g < NE) g_cntE[g] = 0;
    if (g < ND) g_cntD[g] = 0;
}

// ---------------- bucket fill (order within bucket irrelevant for sums) ------
__global__ void k_fill(const int* __restrict__ e_d2e, const int* __restrict__ e_e2d) {
    int e = blockIdx.x * blockDim.x + threadIdx.x;
    if (e >= NEDGE) return;
    {
        int d = e_d2e[NEDGE + e];
        int p = atomicAdd(&g_cntE[d], 1);
        if (p < CAP) g_lstE[d * CAP + p] = e_d2e[e];
    }
    {
        int d = e_e2d[NEDGE + e];
        int p = atomicAdd(&g_cntD[d], 1);
        if (p < CAP) g_lstD[d * CAP + p] = e_e2d[e];
    }
}

// ---------------- mean-gather: warp per (node, batch) ----------------
__global__ void k_agg(const float* __restrict__ SRC, const int* __restrict__ cnt,
                      const int* __restrict__ lst, float* __restrict__ agg,
                      int nNodes, long srcStride) {
    int gw = (blockIdx.x * blockDim.x + threadIdx.x) >> 5;
    if (gw >= nNodes * Bn) return;
    int node = gw % nNodes;
    int b    = gw / nNodes;
    int lane = threadIdx.x & 31;

    int deg = cnt[node];
    int n = deg < CAP ? deg : CAP;
    const int* l = lst + node * CAP;
    float4 a = make_float4(0.f, 0.f, 0.f, 0.f);
    const float* base = SRC + (size_t)b * srcStride;
    for (int j = 0; j < n; ++j) {
        int src = l[j];
        float4 v = reinterpret_cast<const float4*>(base + (size_t)src * H)[lane];
        a.x += v.x; a.y += v.y; a.z += v.z; a.w += v.w;
    }
    float sc = 1.0f / fmaxf((float)deg, 1.0f);
    a.x *= sc; a.y *= sc; a.z *= sc; a.w *= sc;
    reinterpret_cast<float4*>(agg + ((size_t)b * nNodes + node) * H)[lane] = a;
}

// ---------------- GEMM core: 128 thr, 64x128 tile, 8x8/thread, f32x2 ---------
__device__ __forceinline__ void mm_accum(const float* __restrict__ Xs,
                                         const float* __restrict__ Ws,
                                         int tr, int tc, u64 acc[8][4]) {
    const float* xbase = Xs + tr * 8 * 128;
    const float* wbase = Ws + 2 * tc;
#pragma unroll 4
    for (int k = 0; k < 128; k++) {
        u64 wv[4];
#pragma unroll
        for (int j = 0; j < 4; j++)
            wv[j] = *reinterpret_cast<const u64*>(wbase + k * 128 + 32 * j);
#pragma unroll
        for (int i = 0; i < 8; i++) {
            float xv = xbase[i * 128 + k];
            u64 xd;
            asm("mov.b64 %0, {%1, %1};" : "=l"(xd) : "f"(xv));
#pragma unroll
            for (int j = 0; j < 4; j++)
                asm("fma.rn.f32x2 %0, %1, %2, %0;"
                    : "+l"(acc[i][j]) : "l"(wv[j]), "l"(xd));
        }
    }
}

// X tile: 64x128 floats (2048 float4, 128 thr -> 16 iters)
__device__ __forceinline__ void tile_load_x(const float* __restrict__ g,
                                            float* __restrict__ s, int t) {
    const float4* g4 = reinterpret_cast<const float4*>(g);
    float4* s4 = reinterpret_cast<float4*>(s);
#pragma unroll
    for (int i = 0; i < 16; i++) s4[t + 128 * i] = g4[t + 128 * i];
}
// W tile: 128x128 floats (4096 float4 -> 32 iters)
__device__ __forceinline__ void tile_load_w(const float* __restrict__ g,
                                            float* __restrict__ s, int t) {
    const float4* g4 = reinterpret_cast<const float4*>(g);
    float4* s4 = reinterpret_cast<float4*>(s);
#pragma unroll
    for (int i = 0; i < 32; i++) s4[t + 128 * i] = g4[t + 128 * i];
}

#define SMEM_BYTES ((64 * 128 + 128 * 128) * 4)   // 96 KB

// ---------------- MODE 0: Y = X @ Wt ----------------
__global__ void __launch_bounds__(128, 2)
k_gemm0(const float* __restrict__ X, const float* __restrict__ Wt,
        float* __restrict__ out) {
    extern __shared__ float smx[];
    float* Xs = smx;
    float* Ws = smx + 64 * 128;
    const int t = threadIdx.x;
    const size_t row0 = (size_t)blockIdx.x * 64;

    tile_load_x(X + row0 * H, Xs, t);
    tile_load_w(Wt, Ws, t);
    __syncthreads();

    const int tc = t & 15, tr = t >> 4;
    u64 acc[8][4];
#pragma unroll
    for (int i = 0; i < 8; i++)
#pragma unroll
        for (int j = 0; j < 4; j++) acc[i][j] = 0ull;

    mm_accum(Xs, Ws, tr, tc, acc);

#pragma unroll
    for (int i = 0; i < 8; i++) {
        float* orow = out + (row0 + tr * 8 + i) * H + 2 * tc;
#pragma unroll
        for (int j = 0; j < 4; j++)
            *reinterpret_cast<u64*>(orow + 32 * j) = acc[i][j];
    }
}

// ---------------- Phase-1 E-side: self-GEMM + fused gather + LN ----------------
__global__ void __launch_bounds__(128, 2)
k_gemmE(const float* __restrict__ X, const float* __restrict__ Wt,
        const float* __restrict__ Y,
        const int* __restrict__ cnt, const int* __restrict__ lst,
        const float* __restrict__ ew,
        const float* __restrict__ bias, const float* __restrict__ gamma,
        const float* __restrict__ beta, float* __restrict__ out) {
    extern __shared__ float smx[];
    float* Xs = smx;
    float* Ws = smx + 64 * 128;
    const int t = threadIdx.x;
    const size_t row0 = (size_t)blockIdx.x * 64;
    const int b = (int)(row0 / NE);
    const int e0 = (int)(row0 % NE);

    tile_load_x(X + row0 * H, Xs, t);
    tile_load_w(Wt, Ws, t);
    __syncthreads();

    const int tc = t & 15, tr = t >> 4;
    u64 acc[8][4];
#pragma unroll
    for (int i = 0; i < 8; i++)
#pragma unroll
        for (int j = 0; j < 4; j++) acc[i][j] = 0ull;

    mm_accum(Xs, Ws, tr, tc, acc);

    float2 b2[4], g2[4], be2[4];
#pragma unroll
    for (int j = 0; j < 4; j++) {
        b2[j]  = *reinterpret_cast<const float2*>(bias  + 2 * tc + 32 * j);
        g2[j]  = *reinterpret_cast<const float2*>(gamma + 2 * tc + 32 * j);
        be2[j] = *reinterpret_cast<const float2*>(beta  + 2 * tc + 32 * j);
    }
    const float* Yb = Y + (size_t)b * ND * H + 2 * tc;

#pragma unroll
    for (int i = 0; i < 8; i++) {
        const int e = e0 + tr * 8 + i;
        const size_t r = row0 + tr * 8 + i;
        int deg = cnt[e];
        int n = deg < CAP ? deg : CAP;
        const int* l = lst + e * CAP;
        float sc = (1.0f / (1.0f + __expf(-ew[e]))) / fmaxf((float)deg, 1.0f);

        float2 ag[4];
#pragma unroll
        for (int j = 0; j < 4; j++) ag[j] = make_float2(0.f, 0.f);
        for (int p = 0; p < n; ++p) {
            const float* yr = Yb + (size_t)l[p] * H;
#pragma unroll
            for (int j = 0; j < 4; j++) {
                float2 v = *reinterpret_cast<const float2*>(yr + 32 * j);
                ag[j].x += v.x; ag[j].y += v.y;
            }
        }

        float tv[8];
        float ssum = 0.f, q = 0.f;
#pragma unroll
        for (int j = 0; j < 4; j++) {
            float plo, phi;
            asm("mov.b64 {%0, %1}, %2;" : "=f"(plo), "=f"(phi) : "l"(acc[i][j]));
            float2 x2 = *reinterpret_cast<const float2*>(Xs + (tr * 8 + i) * 128 + 2 * tc + 32 * j);
            float t0 = plo + ag[j].x * sc + b2[j].x; t0 = fmaxf(t0, 0.f); t0 += x2.x;
            float t1 = phi + ag[j].y * sc + b2[j].y; t1 = fmaxf(t1, 0.f); t1 += x2.y;
            tv[2 * j] = t0; tv[2 * j + 1] = t1;
            ssum += t0 + t1;
            q += t0 * t0 + t1 * t1;
        }
#pragma unroll
        for (int o = 8; o; o >>= 1) {
            ssum += __shfl_xor_sync(0xffffffffu, ssum, o, 16);
            q    += __shfl_xor_sync(0xffffffffu, q, o, 16);
        }
        float m = ssum * (1.0f / 128.0f);
        float rstd = rsqrtf(q * (1.0f / 128.0f) - m * m + 1e-5f);
        float* orow = out + r * H + 2 * tc;
#pragma unroll
        for (int j = 0; j < 4; j++) {
            float2 o2;
            o2.x = (tv[2 * j]     - m) * rstd * g2[j].x + be2[j].x;
            o2.y = (tv[2 * j + 1] - m) * rstd * g2[j].y + be2[j].y;
            *reinterpret_cast<float2*>(orow + 32 * j) = o2;
        }
    }
}

// ---------------- Phase-2 D-side dual GEMM + LN (X slot reused for A) ---------
__global__ void __launch_bounds__(128, 2)
k_gemmD(const float* __restrict__ X, const float* __restrict__ W1t,
        const float* __restrict__ A, const float* __restrict__ W2t,
        const float* __restrict__ bias, const float* __restrict__ gamma,
        const float* __restrict__ beta, float* __restrict__ out) {
    extern __shared__ float smx[];
    float* Xs = smx;
    float* Ws = smx + 64 * 128;
    const int t = threadIdx.x;
    const size_t row0 = (size_t)blockIdx.x * 64;

    tile_load_x(X + row0 * H, Xs, t);
    tile_load_w(W1t, Ws, t);
    __syncthreads();

    const int tc = t & 15, tr = t >> 4;
    u64 acc[8][4];
#pragma unroll
    for (int i = 0; i < 8; i++)
#pragma unroll
        for (int j = 0; j < 4; j++) acc[i][j] = 0ull;

    mm_accum(Xs, Ws, tr, tc, acc);
    __syncthreads();

    tile_load_x(A + row0 * H, Xs, t);
    tile_load_w(W2t, Ws, t);
    __syncthreads();

    mm_accum(Xs, Ws, tr, tc, acc);

    float2 b2[4], g2[4], be2[4];
#pragma unroll
    for (int j = 0; j < 4; j++) {
        b2[j]  = *reinterpret_cast<const float2*>(bias  + 2 * tc + 32 * j);
        g2[j]  = *reinterpret_cast<const float2*>(gamma + 2 * tc + 32 * j);
        be2[j] = *reinterpret_cast<const float2*>(beta  + 2 * tc + 32 * j);
    }
#pragma unroll
    for (int i = 0; i < 8; i++) {
        const size_t r = row0 + tr * 8 + i;
        float tv[8];
        float ssum = 0.f, q = 0.f;
        const float* xrow = X + r * H + 2 * tc;   // residual (L1-hot within launch)
#pragma unroll
        for (int j = 0; j < 4; j++) {
            float plo, phi;
            asm("mov.b64 {%0, %1}, %2;" : "=f"(plo), "=f"(phi) : "l"(acc[i][j]));
            float2 x2 = *reinterpret_cast<const float2*>(xrow + 32 * j);
            float t0 = plo + b2[j].x; t0 = fmaxf(t0, 0.f); t0 += x2.x;
            float t1 = phi + b2[j].y; t1 = fmaxf(t1, 0.f); t1 += x2.y;
            tv[2 * j] = t0; tv[2 * j + 1] = t1;
            ssum += t0 + t1;
            q += t0 * t0 + t1 * t1;
        }
#pragma unroll
        for (int o = 8; o; o >>= 1) {
            ssum += __shfl_xor_sync(0xffffffffu, ssum, o, 16);
            q    += __shfl_xor_sync(0xffffffffu, q, o, 16);
        }
        float m = ssum * (1.0f / 128.0f);
        float rstd = rsqrtf(q * (1.0f / 128.0f) - m * m + 1e-5f);
        float* orow = out + r * H + 2 * tc;
#pragma unroll
        for (int j = 0; j < 4; j++) {
            float2 o2;
            o2.x = (tv[2 * j]     - m) * rstd * g2[j].x + be2[j].x;
            o2.y = (tv[2 * j + 1] - m) * rstd * g2[j].y + be2[j].y;
            *reinterpret_cast<float2*>(orow + 32 * j) = o2;
        }
    }
}

// ---------------- launch ----------------
extern "C" void kernel_launch(void* const* d_in, const int* in_sizes, int n_in,
                              void* d_out, int out_size) {
    const float* hD    = (const float*)d_in[0];
    const float* hE    = (const float*)d_in[1];
    const int*   e_d2e = (const int*)d_in[2];
    const int*   e_e2d = (const int*)d_in[3];
    const float* ew    = (const float*)d_in[4];
    const float* W_d2e    = (const float*)d_in[5];
    const float* W_e_self = (const float*)d_in[6];
    const float* b_e   = (const float*)d_in[7];
    const float* g_e   = (const float*)d_in[8];
    const float* be_e  = (const float*)d_in[9];
    const float* W_e2d    = (const float*)d_in[10];
    const float* W_d_self = (const float*)d_in[11];
    const float* b_d   = (const float*)d_in[12];
    const float* g_d   = (const float*)d_in[13];
    const float* be_d  = (const float*)d_in[14];

    float* out_hD = (float*)d_out;
    float* out_hE = (float*)d_out + (size_t)Bn * ND * H;

    float *pY, *pAggPre, *pWt;
    int *pCntE, *pLstE, *pCntD, *pLstD;
    cudaGetSymbolAddress((void**)&pY, g_Y);
    cudaGetSymbolAddress((void**)&pAggPre, g_aggPre);
    cudaGetSymbolAddress((void**)&pWt, g_Wt);
    cudaGetSymbolAddress((void**)&pCntE, g_cntE);
    cudaGetSymbolAddress((void**)&pLstE, g_lstE);
    cudaGetSymbolAddress((void**)&pCntD, g_cntD);
    cudaGetSymbolAddress((void**)&pLstD, g_lstD);

    float* Wt_d2e    = pWt + 0 * H * H;
    float* Wt_e_self = pWt + 1 * H * H;
    float* Wt_e2d    = pWt + 2 * H * H;
    float* Wt_d_self = pWt + 3 * H * H;

    cudaFuncSetAttribute(k_gemm0, cudaFuncAttributeMaxDynamicSharedMemorySize, SMEM_BYTES);
    cudaFuncSetAttribute(k_gemmE, cudaFuncAttributeMaxDynamicSharedMemorySize, SMEM_BYTES);
    cudaFuncSetAttribute(k_gemmD, cudaFuncAttributeMaxDynamicSharedMemorySize, SMEM_BYTES);

    // ---- setup: transpose + zero (1 launch), bucket fill (1 launch) ----
    k_prep<<<256, 256>>>(W_d2e, W_e_self, W_e2d, W_d_self, pWt);
    k_fill<<<NEDGE / 256, 256>>>(e_d2e, e_e2d);

    // ---- Phase 1: D -> E ----
    k_gemm0<<<(Bn * ND) / 64, 128, SMEM_BYTES>>>(hD, Wt_d2e, pY);
    k_gemmE<<<(Bn * NE) / 64, 128, SMEM_BYTES>>>(hE, Wt_e_self, pY, pCntE, pLstE, ew,
                                                 b_e, g_e, be_e, out_hE);

    // ---- Phase 2: E -> D (commuted aggregation + dual GEMM) ----
    k_agg<<<(ND * Bn * 32) / 256, 256>>>(out_hE, pCntD, pLstD, pAggPre, ND, (long)NE * H);
    k_gemmD<<<(Bn * ND) / 64, 128, SMEM_BYTES>>>(hD, Wt_d_self, pAggPre, Wt_e2d,
                                                 b_d, g_d, be_d, out_hD);
}

// round 12
// speedup vs baseline: 1.5304x; 1.0174x over previous
#include <cuda_runtime.h>
#include <cstdint>

#define Bn   16
#define ND   8192
#define NE   16384
#define NEDGE 65536
#define H    128
#define CAP  64     // max bucket capacity per node (max degree ~30, P(>64)~0)

typedef unsigned long long u64;

// ---------------- scratch ----------------
__device__ float g_Y[(size_t)Bn * ND * H];       // hD @ W_d2e^T
__device__ float g_aggPre[(size_t)Bn * ND * H];  // mean gather hE_new
__device__ float g_Wt[4 * H * H];                // transposed weights [k][c]

__device__ int g_cntE[NE];
__device__ int g_lstE[NE * CAP];
__device__ int g_cntD[ND];
__device__ int g_lstD[ND * CAP];

// ---------------- setup: weight transpose + counter zero (one kernel) --------
__global__ void k_prep(const float* __restrict__ W0, const float* __restrict__ W1,
                       const float* __restrict__ W2, const float* __restrict__ W3,
                       float* __restrict__ Wt) {
    int g = blockIdx.x * 256 + threadIdx.x;        // 0..65535
    int m = g >> 14;
    int idx = g & 16383;
    int k = idx >> 7, c = idx & 127;
    const float* W = (m == 0) ? W0 : (m == 1) ? W1 : (m == 2) ? W2 : W3;
    Wt[g] = W[c * H + k];
    if (g < NE) g_cntE[g] = 0;
    if (g < ND) g_cntD[g] = 0;
}

// ---------------- bucket fill ----------------
__global__ void k_fill(const int* __restrict__ e_d2e, const int* __restrict__ e_e2d) {
    int e = blockIdx.x * blockDim.x + threadIdx.x;
    if (e >= NEDGE) return;
    {
        int d = e_d2e[NEDGE + e];
        int p = atomicAdd(&g_cntE[d], 1);
        if (p < CAP) g_lstE[d * CAP + p] = e_d2e[e];
    }
    {
        int d = e_e2d[NEDGE + e];
        int p = atomicAdd(&g_cntD[d], 1);
        if (p < CAP) g_lstD[d * CAP + p] = e_e2d[e];
    }
}

// ---------------- mean-gather: warp per (node, batch) ----------------
__global__ void k_agg(const float* __restrict__ SRC, const int* __restrict__ cnt,
                      const int* __restrict__ lst, float* __restrict__ agg,
                      int nNodes, long srcStride) {
    int gw = (blockIdx.x * blockDim.x + threadIdx.x) >> 5;
    if (gw >= nNodes * Bn) return;
    int node = gw % nNodes;
    int b    = gw / nNodes;
    int lane = threadIdx.x & 31;

    int deg = cnt[node];
    int n = deg < CAP ? deg : CAP;
    const int* l = lst + node * CAP;
    float4 a = make_float4(0.f, 0.f, 0.f, 0.f);
    const float* base = SRC + (size_t)b * srcStride;
    for (int j = 0; j < n; ++j) {
        int src = l[j];
        float4 v = reinterpret_cast<const float4*>(base + (size_t)src * H)[lane];
        a.x += v.x; a.y += v.y; a.z += v.z; a.w += v.w;
    }
    float sc = 1.0f / fmaxf((float)deg, 1.0f);
    a.x *= sc; a.y *= sc; a.z *= sc; a.w *= sc;
    reinterpret_cast<float4*>(agg + ((size_t)b * nNodes + node) * H)[lane] = a;
}

// ---------------- GEMM core: 256 thr, 64x128 tile, 4x8/thread, f32x2 ---------
__device__ __forceinline__ void mm_accum(const float* __restrict__ Xs,
                                         const float* __restrict__ Ws,
                                         int tr, int tc, u64 acc[4][4]) {
    const float* xbase = Xs + tr * 4 * 128;
    const float* wbase = Ws + 2 * tc;
#pragma unroll 4
    for (int k = 0; k < 128; k++) {
        u64 wv[4];
#pragma unroll
        for (int j = 0; j < 4; j++)
            wv[j] = *reinterpret_cast<const u64*>(wbase + k * 128 + 32 * j);
#pragma unroll
        for (int i = 0; i < 4; i++) {
            float xv = xbase[i * 128 + k];
            u64 xd;
            asm("mov.b64 %0, {%1, %1};" : "=l"(xd) : "f"(xv));
#pragma unroll
            for (int j = 0; j < 4; j++)
                asm("fma.rn.f32x2 %0, %1, %2, %0;"
                    : "+l"(acc[i][j]) : "l"(wv[j]), "l"(xd));
        }
    }
}

// X tile: 64x128 floats (2048 float4, 256 thr -> 8 iters)
__device__ __forceinline__ void tile_load_x(const float* __restrict__ g,
                                            float* __restrict__ s, int t) {
    const float4* g4 = reinterpret_cast<const float4*>(g);
    float4* s4 = reinterpret_cast<float4*>(s);
#pragma unroll
    for (int i = 0; i < 8; i++) s4[t + 256 * i] = g4[t + 256 * i];
}
// W tile: 128x128 floats (4096 float4 -> 16 iters)
__device__ __forceinline__ void tile_load_w(const float* __restrict__ g,
                                            float* __restrict__ s, int t) {
    const float4* g4 = reinterpret_cast<const float4*>(g);
    float4* s4 = reinterpret_cast<float4*>(s);
#pragma unroll
    for (int i = 0; i < 16; i++) s4[t + 256 * i] = g4[t + 256 * i];
}

#define SMEM_BYTES ((64 * 128 + 128 * 128) * 4)   // 96 KB

// ---------------- MODE 0: Y = X @ Wt ----------------
__global__ void __launch_bounds__(256, 2)
k_gemm0(const float* __restrict__ X, const float* __restrict__ Wt,
        float* __restrict__ out) {
    extern __shared__ float smx[];
    float* Xs = smx;
    float* Ws = smx + 64 * 128;
    const int t = threadIdx.x;
    const size_t row0 = (size_t)blockIdx.x * 64;

    tile_load_x(X + row0 * H, Xs, t);
    tile_load_w(Wt, Ws, t);
    __syncthreads();

    const int tc = t & 15, tr = t >> 4;
    u64 acc[4][4];
#pragma unroll
    for (int i = 0; i < 4; i++)
#pragma unroll
        for (int j = 0; j < 4; j++) acc[i][j] = 0ull;

    mm_accum(Xs, Ws, tr, tc, acc);

#pragma unroll
    for (int i = 0; i < 4; i++) {
        float* orow = out + (row0 + tr * 4 + i) * H + 2 * tc;
#pragma unroll
        for (int j = 0; j < 4; j++)
            *reinterpret_cast<u64*>(orow + 32 * j) = acc[i][j];
    }
}

// ---------------- Phase-1 E-side: self-GEMM + fused gather + LN ----------------
__global__ void __launch_bounds__(256, 2)
k_gemmE(const float* __restrict__ X, const float* __restrict__ Wt,
        const float* __restrict__ Y,
        const int* __restrict__ cnt, const int* __restrict__ lst,
        const float* __restrict__ ew,
        const float* __restrict__ bias, const float* __restrict__ gamma,
        const float* __restrict__ beta, float* __restrict__ out) {
    extern __shared__ float smx[];
    float* Xs = smx;
    float* Ws = smx + 64 * 128;
    const int t = threadIdx.x;
    const size_t row0 = (size_t)blockIdx.x * 64;
    const int b = (int)(row0 / NE);
    const int e0 = (int)(row0 % NE);

    tile_load_x(X + row0 * H, Xs, t);
    tile_load_w(Wt, Ws, t);
    __syncthreads();

    const int tc = t & 15, tr = t >> 4;
    u64 acc[4][4];
#pragma unroll
    for (int i = 0; i < 4; i++)
#pragma unroll
        for (int j = 0; j < 4; j++) acc[i][j] = 0ull;

    mm_accum(Xs, Ws, tr, tc, acc);

    float2 b2[4], g2[4], be2[4];
#pragma unroll
    for (int j = 0; j < 4; j++) {
        b2[j]  = *reinterpret_cast<const float2*>(bias  + 2 * tc + 32 * j);
        g2[j]  = *reinterpret_cast<const float2*>(gamma + 2 * tc + 32 * j);
        be2[j] = *reinterpret_cast<const float2*>(beta  + 2 * tc + 32 * j);
    }
    const float* Yb = Y + (size_t)b * ND * H + 2 * tc;

#pragma unroll
    for (int i = 0; i < 4; i++) {
        const int e = e0 + tr * 4 + i;
        const size_t r = row0 + tr * 4 + i;
        int deg = cnt[e];
        int n = deg < CAP ? deg : CAP;
        const int* l = lst + e * CAP;
        float sc = (1.0f / (1.0f + __expf(-ew[e]))) / fmaxf((float)deg, 1.0f);

        float2 ag[4];
#pragma unroll
        for (int j = 0; j < 4; j++) ag[j] = make_float2(0.f, 0.f);
        for (int p = 0; p < n; ++p) {
            const float* yr = Yb + (size_t)l[p] * H;
#pragma unroll
            for (int j = 0; j < 4; j++) {
                float2 v = *reinterpret_cast<const float2*>(yr + 32 * j);
                ag[j].x += v.x; ag[j].y += v.y;
            }
        }

        float tv[8];
        float ssum = 0.f, q = 0.f;
#pragma unroll
        for (int j = 0; j < 4; j++) {
            float plo, phi;
            asm("mov.b64 {%0, %1}, %2;" : "=f"(plo), "=f"(phi) : "l"(acc[i][j]));
            float2 x2 = *reinterpret_cast<const float2*>(Xs + (tr * 4 + i) * 128 + 2 * tc + 32 * j);
            float t0 = plo + ag[j].x * sc + b2[j].x; t0 = fmaxf(t0, 0.f); t0 += x2.x;
            float t1 = phi + ag[j].y * sc + b2[j].y; t1 = fmaxf(t1, 0.f); t1 += x2.y;
            tv[2 * j] = t0; tv[2 * j + 1] = t1;
            ssum += t0 + t1;
            q += t0 * t0 + t1 * t1;
        }
#pragma unroll
        for (int o = 8; o; o >>= 1) {
            ssum += __shfl_xor_sync(0xffffffffu, ssum, o, 16);
            q    += __shfl_xor_sync(0xffffffffu, q, o, 16);
        }
        float m = ssum * (1.0f / 128.0f);
        float rstd = rsqrtf(q * (1.0f / 128.0f) - m * m + 1e-5f);
        float* orow = out + r * H + 2 * tc;
#pragma unroll
        for (int j = 0; j < 4; j++) {
            float2 o2;
            o2.x = (tv[2 * j]     - m) * rstd * g2[j].x + be2[j].x;
            o2.y = (tv[2 * j + 1] - m) * rstd * g2[j].y + be2[j].y;
            *reinterpret_cast<float2*>(orow + 32 * j) = o2;
        }
    }
}

// ---------------- Phase-2 D-side dual GEMM + LN (X slot reused for A) ---------
__global__ void __launch_bounds__(256, 2)
k_gemmD(const float* __restrict__ X, const float* __restrict__ W1t,
        const float* __restrict__ A, const float* __restrict__ W2t,
        const float* __restrict__ bias, const float* __restrict__ gamma,
        const float* __restrict__ beta, float* __restrict__ out) {
    extern __shared__ float smx[];
    float* Xs = smx;
    float* Ws = smx + 64 * 128;
    const int t = threadIdx.x;
    const size_t row0 = (size_t)blockIdx.x * 64;

    tile_load_x(X + row0 * H, Xs, t);
    tile_load_w(W1t, Ws, t);
    __syncthreads();

    const int tc = t & 15, tr = t >> 4;
    u64 acc[4][4];
#pragma unroll
    for (int i = 0; i < 4; i++)
#pragma unroll
        for (int j = 0; j < 4; j++) acc[i][j] = 0ull;

    mm_accum(Xs, Ws, tr, tc, acc);
    __syncthreads();

    tile_load_x(A + row0 * H, Xs, t);
    tile_load_w(W2t, Ws, t);
    __syncthreads();

    mm_accum(Xs, Ws, tr, tc, acc);

    float2 b2[4], g2[4], be2[4];
#pragma unroll
    for (int j = 0; j < 4; j++) {
        b2[j]  = *reinterpret_cast<const float2*>(bias  + 2 * tc + 32 * j);
        g2[j]  = *reinterpret_cast<const float2*>(gamma + 2 * tc + 32 * j);
        be2[j] = *reinterpret_cast<const float2*>(beta  + 2 * tc + 32 * j);
    }
#pragma unroll
    for (int i = 0; i < 4; i++) {
        const size_t r = row0 + tr * 4 + i;
        float tv[8];
        float ssum = 0.f, q = 0.f;
        const float* xrow = X + r * H + 2 * tc;   // residual (L1/L2-hot)
#pragma unroll
        for (int j = 0; j < 4; j++) {
            float plo, phi;
            asm("mov.b64 {%0, %1}, %2;" : "=f"(plo), "=f"(phi) : "l"(acc[i][j]));
            float2 x2 = *reinterpret_cast<const float2*>(xrow + 32 * j);
            float t0 = plo + b2[j].x; t0 = fmaxf(t0, 0.f); t0 += x2.x;
            float t1 = phi + b2[j].y; t1 = fmaxf(t1, 0.f); t1 += x2.y;
            tv[2 * j] = t0; tv[2 * j + 1] = t1;
            ssum += t0 + t1;
            q += t0 * t0 + t1 * t1;
        }
#pragma unroll
        for (int o = 8; o; o >>= 1) {
            ssum += __shfl_xor_sync(0xffffffffu, ssum, o, 16);
            q    += __shfl_xor_sync(0xffffffffu, q, o, 16);
        }
        float m = ssum * (1.0f / 128.0f);
        float rstd = rsqrtf(q * (1.0f / 128.0f) - m * m + 1e-5f);
        float* orow = out + r * H + 2 * tc;
#pragma unroll
        for (int j = 0; j < 4; j++) {
            float2 o2;
            o2.x = (tv[2 * j]     - m) * rstd * g2[j].x + be2[j].x;
            o2.y = (tv[2 * j + 1] - m) * rstd * g2[j].y + be2[j].y;
            *reinterpret_cast<float2*>(orow + 32 * j) = o2;
        }
    }
}

// ---------------- launch ----------------
extern "C" void kernel_launch(void* const* d_in, const int* in_sizes, int n_in,
                              void* d_out, int out_size) {
    const float* hD    = (const float*)d_in[0];
    const float* hE    = (const float*)d_in[1];
    const int*   e_d2e = (const int*)d_in[2];
    const int*   e_e2d = (const int*)d_in[3];
    const float* ew    = (const float*)d_in[4];
    const float* W_d2e    = (const float*)d_in[5];
    const float* W_e_self = (const float*)d_in[6];
    const float* b_e   = (const float*)d_in[7];
    const float* g_e   = (const float*)d_in[8];
    const float* be_e  = (const float*)d_in[9];
    const float* W_e2d    = (const float*)d_in[10];
    const float* W_d_self = (const float*)d_in[11];
    const float* b_d   = (const float*)d_in[12];
    const float* g_d   = (const float*)d_in[13];
    const float* be_d  = (const float*)d_in[14];

    float* out_hD = (float*)d_out;
    float* out_hE = (float*)d_out + (size_t)Bn * ND * H;

    float *pY, *pAggPre, *pWt;
    int *pCntE, *pLstE, *pCntD, *pLstD;
    cudaGetSymbolAddress((void**)&pY, g_Y);
    cudaGetSymbolAddress((void**)&pAggPre, g_aggPre);
    cudaGetSymbolAddress((void**)&pWt, g_Wt);
    cudaGetSymbolAddress((void**)&pCntE, g_cntE);
    cudaGetSymbolAddress((void**)&pLstE, g_lstE);
    cudaGetSymbolAddress((void**)&pCntD, g_cntD);
    cudaGetSymbolAddress((void**)&pLstD, g_lstD);

    float* Wt_d2e    = pWt + 0 * H * H;
    float* Wt_e_self = pWt + 1 * H * H;
    float* Wt_e2d    = pWt + 2 * H * H;
    float* Wt_d_self = pWt + 3 * H * H;

    cudaFuncSetAttribute(k_gemm0, cudaFuncAttributeMaxDynamicSharedMemorySize, SMEM_BYTES);
    cudaFuncSetAttribute(k_gemmE, cudaFuncAttributeMaxDynamicSharedMemorySize, SMEM_BYTES);
    cudaFuncSetAttribute(k_gemmD, cudaFuncAttributeMaxDynamicSharedMemorySize, SMEM_BYTES);

    // ---- setup ----
    k_prep<<<256, 256>>>(W_d2e, W_e_self, W_e2d, W_d_self, pWt);
    k_fill<<<NEDGE / 256, 256>>>(e_d2e, e_e2d);

    // ---- Phase 1: D -> E ----
    k_gemm0<<<(Bn * ND) / 64, 256, SMEM_BYTES>>>(hD, Wt_d2e, pY);
    k_gemmE<<<(Bn * NE) / 64, 256, SMEM_BYTES>>>(hE, Wt_e_self, pY, pCntE, pLstE, ew,
                                                 b_e, g_e, be_e, out_hE);

    // ---- Phase 2: E -> D (commuted aggregation + dual GEMM) ----
    k_agg<<<(ND * Bn * 32) / 256, 256>>>(out_hE, pCntD, pLstD, pAggPre, ND, (long)NE * H);
    k_gemmD<<<(Bn * ND) / 64, 256, SMEM_BYTES>>>(hD, Wt_d_self, pAggPre, Wt_e2d,
                                                 b_d, g_d, be_d, out_hD);
}

// round 13
// speedup vs baseline: 1.6628x; 1.0865x over previous
#include <cuda_runtime.h>
#include <cstdint>

#define Bn   16
#define ND   8192
#define NE   16384
#define NEDGE 65536
#define H    128
#define CAP  64

typedef unsigned long long u64;
typedef unsigned int u32;

// ---------------- scratch ----------------
__device__ float g_Y[(size_t)Bn * ND * H];
__device__ float g_aggPre[(size_t)Bn * ND * H];
__device__ float g_Wt[4 * H * H];                // transposed weights [k][c]

__device__ int g_cntE[NE];
__device__ int g_lstE[NE * CAP];
__device__ int g_cntD[ND];
__device__ int g_lstD[ND * CAP];

// ---------------- cp.async helpers ----------------
__device__ __forceinline__ u32 cvta_s(const void* p) {
    u32 a;
    asm("{ .reg .u64 t; cvta.to.shared.u64 t, %1; cvt.u32.u64 %0, t; }" : "=r"(a) : "l"(p));
    return a;
}
#define CPA16(s, g)   asm volatile("cp.async.cg.shared.global [%0], [%1], 16;" :: "r"(s), "l"(g) : "memory")
#define CPA_COMMIT()  asm volatile("cp.async.commit_group;" ::: "memory")
#define CPA_WAIT(n)   asm volatile("cp.async.wait_group %0;" :: "n"(n) : "memory")

// 2048 float4 per tile (64x128 floats), 256 thr -> 8 per thread
__device__ __forceinline__ void cpa_tile(u32 sdst, const float* __restrict__ g, int t) {
#pragma unroll
    for (int i = 0; i < 8; i++)
        CPA16(sdst + (u32)(t + 256 * i) * 16u, g + (size_t)(t + 256 * i) * 4);
}

// ---------------- setup ----------------
__global__ void k_prep(const float* __restrict__ W0, const float* __restrict__ W1,
                       const float* __restrict__ W2, const float* __restrict__ W3,
                       float* __restrict__ Wt) {
    int g = blockIdx.x * 256 + threadIdx.x;
    int m = g >> 14;
    int idx = g & 16383;
    int k = idx >> 7, c = idx & 127;
    const float* W = (m == 0) ? W0 : (m == 1) ? W1 : (m == 2) ? W2 : W3;
    Wt[g] = W[c * H + k];
    if (g < NE) g_cntE[g] = 0;
    if (g < ND) g_cntD[g] = 0;
}

__global__ void k_fill(const int* __restrict__ e_d2e, const int* __restrict__ e_e2d) {
    int e = blockIdx.x * blockDim.x + threadIdx.x;
    if (e >= NEDGE) return;
    {
        int d = e_d2e[NEDGE + e];
        int p = atomicAdd(&g_cntE[d], 1);
        if (p < CAP) g_lstE[d * CAP + p] = e_d2e[e];
    }
    {
        int d = e_e2d[NEDGE + e];
        int p = atomicAdd(&g_cntD[d], 1);
        if (p < CAP) g_lstD[d * CAP + p] = e_e2d[e];
    }
}

// ---------------- mean-gather: warp per (node, batch) ----------------
__global__ void k_agg(const float* __restrict__ SRC, const int* __restrict__ cnt,
                      const int* __restrict__ lst, float* __restrict__ agg,
                      int nNodes, long srcStride) {
    int gw = (blockIdx.x * blockDim.x + threadIdx.x) >> 5;
    if (gw >= nNodes * Bn) return;
    int node = gw % nNodes;
    int b    = gw / nNodes;
    int lane = threadIdx.x & 31;

    int deg = cnt[node];
    int n = deg < CAP ? deg : CAP;
    const int* l = lst + node * CAP;
    float4 a = make_float4(0.f, 0.f, 0.f, 0.f);
    const float* base = SRC + (size_t)b * srcStride;
    for (int j = 0; j < n; ++j) {
        int src = l[j];
        float4 v = reinterpret_cast<const float4*>(base + (size_t)src * H)[lane];
        a.x += v.x; a.y += v.y; a.z += v.z; a.w += v.w;
    }
    float sc = 1.0f / fmaxf((float)deg, 1.0f);
    a.x *= sc; a.y *= sc; a.z *= sc; a.w *= sc;
    reinterpret_cast<float4*>(agg + ((size_t)b * nNodes + node) * H)[lane] = a;
}

// ---------------- GEMM inner: one 64-k chunk, vectorized x ----------------
// Xs: 64x128 (row-major), Wc: 64x128 chunk ([k][c]); kb = column base in Xs.
__device__ __forceinline__ void mm_chunk(const float* __restrict__ Xs,
                                         const float* __restrict__ Wc,
                                         int tr, int tc, int kb, u64 acc[4][4]) {
    const float* xb = Xs + tr * 4 * 128 + kb;
    const float* wb = Wc + 2 * tc;
#pragma unroll 2
    for (int k0 = 0; k0 < 64; k0 += 4) {
        float4 xq[4];
#pragma unroll
        for (int i = 0; i < 4; i++)
            xq[i] = *reinterpret_cast<const float4*>(xb + i * 128 + k0);
#pragma unroll
        for (int kk = 0; kk < 4; kk++) {
            u64 wv[4];
#pragma unroll
            for (int j = 0; j < 4; j++)
                wv[j] = *reinterpret_cast<const u64*>(wb + (k0 + kk) * 128 + 32 * j);
#pragma unroll
            for (int i = 0; i < 4; i++) {
                float xs = (kk == 0) ? xq[i].x : (kk == 1) ? xq[i].y
                         : (kk == 2) ? xq[i].z : xq[i].w;
                u64 xd;
                asm("mov.b64 %0, {%1, %1};" : "=l"(xd) : "f"(xs));
#pragma unroll
                for (int j = 0; j < 4; j++)
                    asm("fma.rn.f32x2 %0, %1, %2, %0;"
                        : "+l"(acc[i][j]) : "l"(wv[j]), "l"(xd));
            }
        }
    }
}

#define SMEM_BYTES ((64 * 128 * 3) * 4)   // X + 2 W chunks = 96 KB

// ---------------- MODE 0: Y = X @ Wt ----------------
__global__ void __launch_bounds__(256, 2)
k_gemm0(const float* __restrict__ X, const float* __restrict__ Wt,
        float* __restrict__ out) {
    extern __shared__ float smx[];
    float* Xs = smx;
    float* Wc0 = smx + 64 * 128;
    float* Wc1 = smx + 2 * 64 * 128;
    const int t = threadIdx.x;
    const size_t row0 = (size_t)blockIdx.x * 64;

    const u32 sX = cvta_s(Xs), sW0 = cvta_s(Wc0), sW1 = cvta_s(Wc1);
    cpa_tile(sX, X + row0 * H, t);
    cpa_tile(sW0, Wt, t);
    CPA_COMMIT();
    cpa_tile(sW1, Wt + 64 * 128, t);
    CPA_COMMIT();

    const int tc = t & 15, tr = t >> 4;
    u64 acc[4][4];
#pragma unroll
    for (int i = 0; i < 4; i++)
#pragma unroll
        for (int j = 0; j < 4; j++) acc[i][j] = 0ull;

    CPA_WAIT(1);
    __syncthreads();
    mm_chunk(Xs, Wc0, tr, tc, 0, acc);
    CPA_WAIT(0);
    __syncthreads();
    mm_chunk(Xs, Wc1, tr, tc, 64, acc);

#pragma unroll
    for (int i = 0; i < 4; i++) {
        float* orow = out + (row0 + tr * 4 + i) * H + 2 * tc;
#pragma unroll
        for (int j = 0; j < 4; j++)
            *reinterpret_cast<u64*>(orow + 32 * j) = acc[i][j];
    }
}

// ---------------- Phase-1 E-side: self-GEMM + fused gather + LN ----------------
__global__ void __launch_bounds__(256, 2)
k_gemmE(const float* __restrict__ X, const float* __restrict__ Wt,
        const float* __restrict__ Y,
        const int* __restrict__ cnt, const int* __restrict__ lst,
        const float* __restrict__ ew,
        const float* __restrict__ bias, const float* __restrict__ gamma,
        const float* __restrict__ beta, float* __restrict__ out) {
    extern __shared__ float smx[];
    float* Xs = smx;
    float* Wc0 = smx + 64 * 128;
    float* Wc1 = smx + 2 * 64 * 128;
    const int t = threadIdx.x;
    const size_t row0 = (size_t)blockIdx.x * 64;
    const int b = (int)(row0 / NE);
    const int e0 = (int)(row0 % NE);

    const u32 sX = cvta_s(Xs), sW0 = cvta_s(Wc0), sW1 = cvta_s(Wc1);
    cpa_tile(sX, X + row0 * H, t);
    cpa_tile(sW0, Wt, t);
    CPA_COMMIT();
    cpa_tile(sW1, Wt + 64 * 128, t);
    CPA_COMMIT();

    const int tc = t & 15, tr = t >> 4;
    u64 acc[4][4];
#pragma unroll
    for (int i = 0; i < 4; i++)
#pragma unroll
        for (int j = 0; j < 4; j++) acc[i][j] = 0ull;

    CPA_WAIT(1);
    __syncthreads();
    mm_chunk(Xs, Wc0, tr, tc, 0, acc);
    CPA_WAIT(0);
    __syncthreads();
    mm_chunk(Xs, Wc1, tr, tc, 64, acc);

    float2 b2[4], g2[4], be2[4];
#pragma unroll
    for (int j = 0; j < 4; j++) {
        b2[j]  = *reinterpret_cast<const float2*>(bias  + 2 * tc + 32 * j);
        g2[j]  = *reinterpret_cast<const float2*>(gamma + 2 * tc + 32 * j);
        be2[j] = *reinterpret_cast<const float2*>(beta  + 2 * tc + 32 * j);
    }
    const float* Yb = Y + (size_t)b * ND * H + 2 * tc;

#pragma unroll
    for (int i = 0; i < 4; i++) {
        const int e = e0 + tr * 4 + i;
        const size_t r = row0 + tr * 4 + i;
        int deg = cnt[e];
        int n = deg < CAP ? deg : CAP;
        const int* l = lst + e * CAP;
        float sc = (1.0f / (1.0f + __expf(-ew[e]))) / fmaxf((float)deg, 1.0f);

        float2 ag[4];
#pragma unroll
        for (int j = 0; j < 4; j++) ag[j] = make_float2(0.f, 0.f);
        for (int p = 0; p < n; ++p) {
            const float* yr = Yb + (size_t)l[p] * H;
#pragma unroll
            for (int j = 0; j < 4; j++) {
                float2 v = *reinterpret_cast<const float2*>(yr + 32 * j);
                ag[j].x += v.x; ag[j].y += v.y;
            }
        }

        float tv[8];
        float ssum = 0.f, q = 0.f;
#pragma unroll
        for (int j = 0; j < 4; j++) {
            float plo, phi;
            asm("mov.b64 {%0, %1}, %2;" : "=f"(plo), "=f"(phi) : "l"(acc[i][j]));
            float2 x2 = *reinterpret_cast<const float2*>(Xs + (tr * 4 + i) * 128 + 2 * tc + 32 * j);
            float t0 = plo + ag[j].x * sc + b2[j].x; t0 = fmaxf(t0, 0.f); t0 += x2.x;
            float t1 = phi + ag[j].y * sc + b2[j].y; t1 = fmaxf(t1, 0.f); t1 += x2.y;
            tv[2 * j] = t0; tv[2 * j + 1] = t1;
            ssum += t0 + t1;
            q += t0 * t0 + t1 * t1;
        }
#pragma unroll
        for (int o = 8; o; o >>= 1) {
            ssum += __shfl_xor_sync(0xffffffffu, ssum, o, 16);
            q    += __shfl_xor_sync(0xffffffffu, q, o, 16);
        }
        float m = ssum * (1.0f / 128.0f);
        float rstd = rsqrtf(q * (1.0f / 128.0f) - m * m + 1e-5f);
        float* orow = out + r * H + 2 * tc;
#pragma unroll
        for (int j = 0; j < 4; j++) {
            float2 o2;
            o2.x = (tv[2 * j]     - m) * rstd * g2[j].x + be2[j].x;
            o2.y = (tv[2 * j + 1] - m) * rstd * g2[j].y + be2[j].y;
            *reinterpret_cast<float2*>(orow + 32 * j) = o2;
        }
    }
}

// ---------------- Phase-2 D-side dual GEMM + LN ----------------
__global__ void __launch_bounds__(256, 2)
k_gemmD(const float* __restrict__ X, const float* __restrict__ W1t,
        const float* __restrict__ A, const float* __restrict__ W2t,
        const float* __restrict__ bias, const float* __restrict__ gamma,
        const float* __restrict__ beta, float* __restrict__ out) {
    extern __shared__ float smx[];
    float* Xs = smx;
    float* Wc0 = smx + 64 * 128;
    float* Wc1 = smx + 2 * 64 * 128;
    const int t = threadIdx.x;
    const size_t row0 = (size_t)blockIdx.x * 64;

    const u32 sX = cvta_s(Xs), sW0 = cvta_s(Wc0), sW1 = cvta_s(Wc1);
    cpa_tile(sX, X + row0 * H, t);
    cpa_tile(sW0, W1t, t);
    CPA_COMMIT();
    cpa_tile(sW1, W1t + 64 * 128, t);
    CPA_COMMIT();

    const int tc = t & 15, tr = t >> 4;
    u64 acc[4][4];
#pragma unroll
    for (int i = 0; i < 4; i++)
#pragma unroll
        for (int j = 0; j < 4; j++) acc[i][j] = 0ull;

    // pass 1 chunk 0
    CPA_WAIT(1);
    __syncthreads();
    mm_chunk(Xs, Wc0, tr, tc, 0, acc);
    // Wc0 free -> stream in W2 chunk 0 while computing pass-1 chunk 1
    CPA_WAIT(0);
    __syncthreads();
    cpa_tile(sW0, W2t, t);
    CPA_COMMIT();
    mm_chunk(Xs, Wc1, tr, tc, 64, acc);
    // Xs + Wc1 free -> load A tile + W2 chunk 1
    __syncthreads();
    cpa_tile(sX, A + row0 * H, t);
    cpa_tile(sW1, W2t + 64 * 128, t);
    CPA_COMMIT();
    CPA_WAIT(0);
    __syncthreads();
    mm_chunk(Xs, Wc0, tr, tc, 0, acc);
    mm_chunk(Xs, Wc1, tr, tc, 64, acc);

    float2 b2[4], g2[4], be2[4];
#pragma unroll
    for (int j = 0; j < 4; j++) {
        b2[j]  = *reinterpret_cast<const float2*>(bias  + 2 * tc + 32 * j);
        g2[j]  = *reinterpret_cast<const float2*>(gamma + 2 * tc + 32 * j);
        be2[j] = *reinterpret_cast<const float2*>(beta  + 2 * tc + 32 * j);
    }
#pragma unroll
    for (int i = 0; i < 4; i++) {
        const size_t r = row0 + tr * 4 + i;
        float tv[8];
        float ssum = 0.f, q = 0.f;
        const float* xrow = X + r * H + 2 * tc;   // residual (L2-hot)
#pragma unroll
        for (int j = 0; j < 4; j++) {
            float plo, phi;
            asm("mov.b64 {%0, %1}, %2;" : "=f"(plo), "=f"(phi) : "l"(acc[i][j]));
            float2 x2 = *reinterpret_cast<const float2*>(xrow + 32 * j);
            float t0 = plo + b2[j].x; t0 = fmaxf(t0, 0.f); t0 += x2.x;
            float t1 = phi + b2[j].y; t1 = fmaxf(t1, 0.f); t1 += x2.y;
            tv[2 * j] = t0; tv[2 * j + 1] = t1;
            ssum += t0 + t1;
            q += t0 * t0 + t1 * t1;
        }
#pragma unroll
        for (int o = 8; o; o >>= 1) {
            ssum += __shfl_xor_sync(0xffffffffu, ssum, o, 16);
            q    += __shfl_xor_sync(0xffffffffu, q, o, 16);
        }
        float m = ssum * (1.0f / 128.0f);
        float rstd = rsqrtf(q * (1.0f / 128.0f) - m * m + 1e-5f);
        float* orow = out + r * H + 2 * tc;
#pragma unroll
        for (int j = 0; j < 4; j++) {
            float2 o2;
            o2.x = (tv[2 * j]     - m) * rstd * g2[j].x + be2[j].x;
            o2.y = (tv[2 * j + 1] - m) * rstd * g2[j].y + be2[j].y;
            *reinterpret_cast<float2*>(orow + 32 * j) = o2;
        }
    }
}

// ---------------- launch ----------------
extern "C" void kernel_launch(void* const* d_in, const int* in_sizes, int n_in,
                              void* d_out, int out_size) {
    const float* hD    = (const float*)d_in[0];
    const float* hE    = (const float*)d_in[1];
    const int*   e_d2e = (const int*)d_in[2];
    const int*   e_e2d = (const int*)d_in[3];
    const float* ew    = (const float*)d_in[4];
    const float* W_d2e    = (const float*)d_in[5];
    const float* W_e_self = (const float*)d_in[6];
    const float* b_e   = (const float*)d_in[7];
    const float* g_e   = (const float*)d_in[8];
    const float* be_e  = (const float*)d_in[9];
    const float* W_e2d    = (const float*)d_in[10];
    const float* W_d_self = (const float*)d_in[11];
    const float* b_d   = (const float*)d_in[12];
    const float* g_d   = (const float*)d_in[13];
    const float* be_d  = (const float*)d_in[14];

    float* out_hD = (float*)d_out;
    float* out_hE = (float*)d_out + (size_t)Bn * ND * H;

    float *pY, *pAggPre, *pWt;
    int *pCntE, *pLstE, *pCntD, *pLstD;
    cudaGetSymbolAddress((void**)&pY, g_Y);
    cudaGetSymbolAddress((void**)&pAggPre, g_aggPre);
    cudaGetSymbolAddress((void**)&pWt, g_Wt);
    cudaGetSymbolAddress((void**)&pCntE, g_cntE);
    cudaGetSymbolAddress((void**)&pLstE, g_lstE);
    cudaGetSymbolAddress((void**)&pCntD, g_cntD);
    cudaGetSymbolAddress((void**)&pLstD, g_lstD);

    float* Wt_d2e    = pWt + 0 * H * H;
    float* Wt_e_self = pWt + 1 * H * H;
    float* Wt_e2d    = pWt + 2 * H * H;
    float* Wt_d_self = pWt + 3 * H * H;

    cudaFuncSetAttribute(k_gemm0, cudaFuncAttributeMaxDynamicSharedMemorySize, SMEM_BYTES);
    cudaFuncSetAttribute(k_gemmE, cudaFuncAttributeMaxDynamicSharedMemorySize, SMEM_BYTES);
    cudaFuncSetAttribute(k_gemmD, cudaFuncAttributeMaxDynamicSharedMemorySize, SMEM_BYTES);

    // ---- setup ----
    k_prep<<<256, 256>>>(W_d2e, W_e_self, W_e2d, W_d_self, pWt);
    k_fill<<<NEDGE / 256, 256>>>(e_d2e, e_e2d);

    // ---- Phase 1: D -> E ----
    k_gemm0<<<(Bn * ND) / 64, 256, SMEM_BYTES>>>(hD, Wt_d2e, pY);
    k_gemmE<<<(Bn * NE) / 64, 256, SMEM_BYTES>>>(hE, Wt_e_self, pY, pCntE, pLstE, ew,
                                                 b_e, g_e, be_e, out_hE);

    // ---- Phase 2: E -> D (commuted aggregation + dual GEMM) ----
    k_agg<<<(ND * Bn * 32) / 256, 256>>>(out_hE, pCntD, pLstD, pAggPre, ND, (long)NE * H);
    k_gemmD<<<(Bn * ND) / 64, 256, SMEM_BYTES>>>(hD, Wt_d_self, pAggPre, Wt_e2d,
                                                 b_d, g_d, be_d, out_hD);
}